// round 9
// baseline (speedup 1.0000x reference)
#include <cuda_runtime.h>
#include <cstdint>

// Problem constants (fixed: N=4, M=8192, D=64, k=16)
#define NB 4
#define MP 8192
#define DD 64
#define KNN 16
#define TM 128
#define TN 64
#define NTILES (MP / TN)        // 128
#define NTHREADS 256
#define NEDGES (NB * MP * KNN)  // 524288

// smem layout (float offsets)
#define SM_A    0                          // A: TM x DD, row-major, chunk-swizzled (32KB)
#define SM_B    (TM * DD)                  // B: 2 buffers x TN x DD (32KB)
#define SM_VALS (SM_B + 2 * TN * DD)       // vals: TM x 16 (8KB)
#define SM_IDX  (SM_VALS + TM * KNN)       // idx:  TM x 16 (8KB)
#define SM_X2R  (SM_IDX + TM * KNN)
#define SM_X2C  (SM_X2R + TM)
#define SMEM_FLOATS (SM_X2C + TN)
#define SMEM_BYTES  (SMEM_FLOATS * 4)      // 82,688 B -> 2 CTAs/SM

typedef unsigned long long ull;

__device__ __forceinline__ ull ffma2(ull a, ull b, ull c) {
    ull d;
    asm("fma.rn.f32x2 %0, %1, %2, %3;" : "=l"(d) : "l"(a), "l"(b), "l"(c));
    return d;
}
__device__ __forceinline__ float lane_lo(ull v) { return __uint_as_float((unsigned)v); }
__device__ __forceinline__ float lane_hi(ull v) { return __uint_as_float((unsigned)(v >> 32)); }

__device__ __forceinline__ void cp16(uint32_t dst, const void* src) {
    asm volatile("cp.async.cg.shared.global [%0], [%1], 16;" :: "r"(dst), "l"(src));
}

__global__ __launch_bounds__(NTHREADS, 2)
void knn_topk_kernel(const float* __restrict__ x,
                     float* __restrict__ out,
                     int write_dst) {
    extern __shared__ float sm[];
    float* As   = sm + SM_A;
    float* Bs   = sm + SM_B;
    float* vals = sm + SM_VALS;
    int*   idxw = (int*)(sm + SM_IDX);
    float* x2r  = sm + SM_X2R;
    float* x2c  = sm + SM_X2C;

    const int tid   = threadIdx.x;
    const int batch = blockIdx.x >> 6;          // 64 row-tiles per batch
    const int rtile = blockIdx.x & 63;
    const float* xb = x + (size_t)batch * MP * DD;
    const int row0  = rtile * TM;

    const uint32_t sm_u32 = (uint32_t)__cvta_generic_to_shared(sm);
    const uint32_t A_u32  = sm_u32 + SM_A * 4;
    const uint32_t B_u32  = sm_u32 + SM_B * 4;

    // ---- init top-16 lists ----
    #pragma unroll
    for (int i = 0; i < 8; ++i) {
        int e = i * NTHREADS + tid;             // 0..2047
        vals[e] = __int_as_float(0x7f800000);
        idxw[e] = 0;
    }

    // ---- cp.async: A tile + B tile 0 (group 0), B tile 1 (group 1) ----
    // chunk-swizzle within a row: chunk c -> c ^ ((row>>2)&7); conflict-free GEMM reads.
    #pragma unroll
    for (int it = 0; it < 8; ++it) {
        int idx = it * NTHREADS + tid;          // 2048 chunks
        int m = idx >> 4, c = idx & 15;
        cp16(A_u32 + (uint32_t)(m * 16 + (c ^ ((m >> 2) & 7))) * 16,
             xb + (size_t)(row0 + m) * DD + c * 4);
    }
    #pragma unroll
    for (int it = 0; it < 4; ++it) {
        int idx = it * NTHREADS + tid;          // 1024 chunks
        int n = idx >> 4, c = idx & 15;
        cp16(B_u32 + (uint32_t)(n * 16 + (c ^ ((n >> 2) & 7))) * 16,
             xb + (size_t)n * DD + c * 4);
    }
    asm volatile("cp.async.commit_group;");
    #pragma unroll
    for (int it = 0; it < 4; ++it) {
        int idx = it * NTHREADS + tid;
        int n = idx >> 4, c = idx & 15;
        cp16(B_u32 + (uint32_t)(TN * DD) * 4 + (uint32_t)(n * 16 + (c ^ ((n >> 2) & 7))) * 16,
             xb + (size_t)(TN + n) * DD + c * 4);
    }
    asm volatile("cp.async.commit_group;");

    // ---- row norms from gmem (L2-resident), sequential-d order ----
    if (tid < TM) {
        const float4* p = reinterpret_cast<const float4*>(xb + (size_t)(row0 + tid) * DD);
        float s = 0.f;
        #pragma unroll
        for (int q = 0; q < 16; ++q) {
            float4 v = p[q];
            s = fmaf(v.x, v.x, s); s = fmaf(v.y, v.y, s);
            s = fmaf(v.z, v.z, s); s = fmaf(v.w, v.w, s);
        }
        x2r[tid] = s;
    }

    asm volatile("cp.async.wait_group %0;" :: "n"(1));   // A + B0 ready
    __syncthreads();

    const int ty = tid >> 4;          // 0..15 -> rows r0..r0+7
    const int tx = tid & 15;          // 0..15 -> cols c0..c0+3
    const int r0 = ty * 8;
    const int c0 = tx * 4;
    const unsigned lane = tid & 31;
    const unsigned hm   = 0xFFFFu << (lane & 16);   // half-warp owning these rows

    for (int ct = 0; ct < NTILES; ++ct) {
        const int col0 = ct * TN;
        const float* Bc = Bs + (ct & 1) * (TN * DD);

        // candidate norms for this tile (gmem, sequential-d order)
        if (tid < TN) {
            const float4* p = reinterpret_cast<const float4*>(xb + (size_t)(col0 + tid) * DD);
            float s = 0.f;
            #pragma unroll
            for (int q = 0; q < 16; ++q) {
                float4 v = p[q];
                s = fmaf(v.x, v.x, s); s = fmaf(v.y, v.y, s);
                s = fmaf(v.z, v.z, s); s = fmaf(v.w, v.w, s);
            }
            x2c[tid] = s;
        }

        // ---- 128x64x64 GEMM, 8x4 micro-tile, k-paired f32x2 (no splats) ----
        ull acc[8][4];
        #pragma unroll
        for (int i = 0; i < 8; ++i)
            #pragma unroll
            for (int j = 0; j < 4; ++j) acc[i][j] = 0ULL;

        #pragma unroll
        for (int c4 = 0; c4 < 16; ++c4) {
            ulonglong2 bv[4];
            #pragma unroll
            for (int j = 0; j < 4; ++j) {
                int n = c0 + j;   // n>>2 == tx
                bv[j] = *reinterpret_cast<const ulonglong2*>(
                    Bc + n * DD + (c4 ^ (tx & 7)) * 4);
            }
            #pragma unroll
            for (int i = 0; i < 8; ++i) {
                int m = r0 + i;
                ulonglong2 av = *reinterpret_cast<const ulonglong2*>(
                    As + m * DD + (c4 ^ ((m >> 2) & 7)) * 4);   // broadcast across tx
                #pragma unroll
                for (int j = 0; j < 4; ++j) {
                    acc[i][j] = ffma2(av.x, bv[j].x, acc[i][j]);
                    acc[i][j] = ffma2(av.y, bv[j].y, acc[i][j]);
                }
            }
        }
        __syncthreads();    // GEMM reads of Bc done; x2c visible

        // prefetch tile ct+2 into the buffer we just finished reading
        bool issued = (ct + 2 < NTILES);
        if (issued) {
            const int col2 = (ct + 2) * TN;
            #pragma unroll
            for (int it = 0; it < 4; ++it) {
                int idx = it * NTHREADS + tid;
                int n = idx >> 4, c = idx & 15;
                cp16(B_u32 + (uint32_t)((ct & 1) * TN * DD) * 4
                           + (uint32_t)(n * 16 + (c ^ ((n >> 2) & 7))) * 16,
                     xb + (size_t)(col2 + n) * DD + c * 4);
            }
            asm volatile("cp.async.commit_group;");
        }

        // ---- fused epilogue: d2 in regs -> filter vs row tau -> ballot insert ----
        #pragma unroll
        for (int rr = 0; rr < 8; ++rr) {
            const int row = r0 + rr;
            const float xr = x2r[row];
            float d2v[4];
            float tauv = vals[row * KNN + 15];
            bool any = false;
            #pragma unroll
            for (int j = 0; j < 4; ++j) {
                float dot = lane_lo(acc[rr][j]) + lane_hi(acc[rr][j]);
                d2v[j] = fmaf(-2.f, dot, xr + x2c[c0 + j]);
                any |= (d2v[j] < tauv);
            }
            unsigned bal = __ballot_sync(hm, any);
            while (bal) {
                unsigned leader = (unsigned)__ffs((int)bal) - 1u;
                bal &= bal - 1u;
                if (lane == leader) {
                    float* rv = vals + row * KNN;
                    int*   ri = idxw + row * KNN;
                    #pragma unroll
                    for (int j = 0; j < 4; ++j) {
                        float v = d2v[j];
                        if (v < rv[KNN - 1]) {          // strict: stable ties
                            int pos = KNN - 1;
                            while (pos > 0 && rv[pos - 1] > v) {
                                rv[pos] = rv[pos - 1];
                                ri[pos] = ri[pos - 1];
                                --pos;
                            }
                            rv[pos] = v;
                            ri[pos] = col0 + c0 + j;
                        }
                    }
                }
                __syncwarp(hm);
            }
        }

        if (issued) asm volatile("cp.async.wait_group %0;" :: "n"(1));
        else        asm volatile("cp.async.wait_group %0;" :: "n"(0));
        __syncthreads();    // epilogue x2c reads done; next buffer visible
    }

    // ---- writeback (float32 output: [src | dst]) ----
    if (tid < TM) {
        const int gid  = batch * MP + row0 + tid;
        const int base = gid * KNN;
        const int off  = batch * MP;
        #pragma unroll
        for (int t = 0; t < KNN; ++t) {
            out[base + t] = (float)(idxw[tid * KNN + t] + off);
        }
        if (write_dst) {
            float fg = (float)gid;
            #pragma unroll
            for (int t = 0; t < KNN; ++t) out[NEDGES + base + t] = fg;
        }
    }
}

extern "C" void kernel_launch(void* const* d_in, const int* in_sizes, int n_in,
                              void* d_out, int out_size) {
    // Bind x = largest input (robust to ordering and element/byte units).
    const float* x = (const float*)d_in[0];
    long long best_sz = -1;
    for (int i = 0; i < n_in; ++i) {
        if ((long long)in_sizes[i] > best_sz) {
            best_sz = in_sizes[i];
            x = (const float*)d_in[i];
        }
    }
    const int write_dst = (out_size >= 2 * NEDGES);

    cudaFuncSetAttribute(knn_topk_kernel,
                         cudaFuncAttributeMaxDynamicSharedMemorySize, SMEM_BYTES);
    knn_topk_kernel<<<NB * (MP / TM), NTHREADS, SMEM_BYTES>>>(x, (float*)d_out, write_dst);
}

// round 10
// speedup vs baseline: 1.4845x; 1.4845x over previous
#include <cuda_runtime.h>

// Problem constants (fixed: N=4, M=8192, D=64, k=16)
#define NB 4
#define MP 8192
#define DD 64
#define KNN 16
#define TM 128
#define TN 64
#define NTILES (MP / TN)        // 128
#define NTHREADS 256
#define NEDGES (NB * MP * KNN)  // 524288

#define PA 132   // At pitch (floats)
#define PB 68    // Bt pitch
#define PD 67    // Dt pitch (odd -> conflict-free row scan)

// shared layout (float offsets)
#define SM_AT  0
#define SM_BT  (DD * PA)                    // 8448
#define SM_DT  (SM_BT + DD * PB)            // + 4352
#define SM_X2R (SM_DT + TM * PD)            // + 8576
#define SM_X2C (SM_X2R + TM)
#define SMEM_FLOATS (SM_X2C + TN)
#define SMEM_BYTES  (SMEM_FLOATS * 4)       // 86,272 B -> 2 CTAs/SM

typedef unsigned long long ull;

__device__ __forceinline__ ull ffma2(ull a, ull b, ull c) {
    ull d;
    asm("fma.rn.f32x2 %0, %1, %2, %3;" : "=l"(d) : "l"(a), "l"(b), "l"(c));
    return d;
}
__device__ __forceinline__ ull splat2(float v) {
    ull d;
    unsigned u = __float_as_uint(v);
    asm("mov.b64 %0, {%1, %1};" : "=l"(d) : "r"(u));
    return d;
}
__device__ __forceinline__ float lane_lo(ull v) { return __uint_as_float((unsigned)v); }
__device__ __forceinline__ float lane_hi(ull v) { return __uint_as_float((unsigned)(v >> 32)); }

__global__ __launch_bounds__(NTHREADS, 2)
void knn_topk_kernel(const float* __restrict__ x,
                     float* __restrict__ out,
                     int write_dst) {
    extern __shared__ float sm[];
    float* At  = sm + SM_AT;    // [64][PA]  At[d][m], m=0..127
    float* Bt  = sm + SM_BT;    // [64][PB]  Bt[d][n], n=0..63
    float* Dt  = sm + SM_DT;    // [128][PD] d2 tile
    float* x2r = sm + SM_X2R;
    float* x2c = sm + SM_X2C;

    const int tid   = threadIdx.x;
    const int batch = blockIdx.x >> 6;          // 64 row-tiles per batch
    const int rtile = blockIdx.x & 63;
    const float* xb = x + (size_t)batch * MP * DD;
    const int row0  = rtile * TM;

    // ---- Prologue: A tile transposed to d-major ----
    #pragma unroll
    for (int it = 0; it < 8; ++it) {
        int idx = it * NTHREADS + tid;          // 0..2047
        int m   = idx & 127;
        int d4  = idx >> 7;                     // 0..15
        float4 v = *reinterpret_cast<const float4*>(xb + (size_t)(row0 + m) * DD + d4 * 4);
        At[(d4 * 4 + 0) * PA + m] = v.x;
        At[(d4 * 4 + 1) * PA + m] = v.y;
        At[(d4 * 4 + 2) * PA + m] = v.z;
        At[(d4 * 4 + 3) * PA + m] = v.w;
    }
    // ---- B tile 0: prefetch to regs, store ----
    float4 pf[4];
    #pragma unroll
    for (int it = 0; it < 4; ++it) {
        int idx = it * NTHREADS + tid;          // 0..1023
        int n   = idx & 63;
        int d4  = idx >> 6;
        pf[it] = *reinterpret_cast<const float4*>(xb + (size_t)n * DD + d4 * 4);
    }
    #pragma unroll
    for (int it = 0; it < 4; ++it) {
        int idx = it * NTHREADS + tid;
        int n   = idx & 63;
        int d4  = idx >> 6;
        Bt[(d4 * 4 + 0) * PB + n] = pf[it].x;
        Bt[(d4 * 4 + 1) * PB + n] = pf[it].y;
        Bt[(d4 * 4 + 2) * PB + n] = pf[it].z;
        Bt[(d4 * 4 + 3) * PB + n] = pf[it].w;
    }
    __syncthreads();

    const int ty = tid >> 4;          // 0..15
    const int tx = tid & 15;          // 0..15
    const int r0 = ty * 8;            // 8 contiguous rows
    const int c0 = tx * 4;            // 4 contiguous cols

    // scan: 2 threads per row, 32 cols each
    const int srow = tid & 127;
    const int sh   = tid >> 7;        // 0 or 1
    const float* drow = &Dt[srow * PD + sh * 32];

    float best[KNN];
    int   bidx[KNN];
    #pragma unroll
    for (int i = 0; i < KNN; ++i) { best[i] = __int_as_float(0x7f800000); bidx[i] = 0; }

    for (int ct = 0; ct < NTILES; ++ct) {
        // ================= P1: scan(ct-1) | norms | prefetch | GEMM(ct) ======
        if (ct > 0) {
            const int cbase = (ct - 1) * TN + sh * 32;
            float b15 = best[KNN - 1];
            #pragma unroll 4
            for (int c = 0; c < 32; ++c) {
                float v = drow[c];
                if (v < b15) {
                    best[KNN - 1] = v;
                    bidx[KNN - 1] = cbase + c;
                    #pragma unroll
                    for (int j = KNN - 1; j > 0; --j) {
                        if (best[j] < best[j - 1]) {
                            float tv = best[j]; best[j] = best[j - 1]; best[j - 1] = tv;
                            int   ti = bidx[j]; bidx[j] = bidx[j - 1]; bidx[j - 1] = ti;
                        }
                    }
                    b15 = best[KNN - 1];
                }
            }
        }
        if (tid < TM && ct == 0) {            // row norms once
            float s = 0.f;
            #pragma unroll
            for (int d = 0; d < DD; ++d) { float a = At[d * PA + tid]; s = fmaf(a, a, s); }
            x2r[tid] = s;
        }
        if (tid < TN) {                        // candidate norms for this tile
            float s = 0.f;
            #pragma unroll
            for (int d = 0; d < DD; ++d) { float b = Bt[d * PB + tid]; s = fmaf(b, b, s); }
            x2c[tid] = s;
        }
        // prefetch next B tile (hidden under GEMM)
        if (ct + 1 < NTILES) {
            const int col0n = (ct + 1) * TN;
            #pragma unroll
            for (int it = 0; it < 4; ++it) {
                int idx = it * NTHREADS + tid;
                int n   = idx & 63;
                int d4  = idx >> 6;
                pf[it] = *reinterpret_cast<const float4*>(xb + (size_t)(col0n + n) * DD + d4 * 4);
            }
        }

        // ---- 128x64x64 GEMM, 8x4 micro-tile, packed f32x2 (rows paired) ----
        ull acc[4][4];
        #pragma unroll
        for (int ip = 0; ip < 4; ++ip)
            #pragma unroll
            for (int j = 0; j < 4; ++j) acc[ip][j] = 0ULL;

        #pragma unroll 4
        for (int k = 0; k < DD; ++k) {
            ulonglong2 a01 = *reinterpret_cast<const ulonglong2*>(&At[k * PA + r0]);
            ulonglong2 a23 = *reinterpret_cast<const ulonglong2*>(&At[k * PA + r0 + 4]);
            float4 bv = *reinterpret_cast<const float4*>(&Bt[k * PB + c0]);
            ull ap[4] = {a01.x, a01.y, a23.x, a23.y};
            float bs[4] = {bv.x, bv.y, bv.z, bv.w};
            #pragma unroll
            for (int j = 0; j < 4; ++j) {
                ull b2 = splat2(bs[j]);
                #pragma unroll
                for (int ip = 0; ip < 4; ++ip)
                    acc[ip][j] = ffma2(ap[ip], b2, acc[ip][j]);
            }
        }
        __syncthreads();   // GEMM reads of Bt done; x2c (and x2r) visible

        // ================= P2: epilogue -> Dt | store prefetched Bt ==========
        {
            float xc[4];
            #pragma unroll
            for (int j = 0; j < 4; ++j) xc[j] = x2c[c0 + j];
            #pragma unroll
            for (int ip = 0; ip < 4; ++ip) {
                int ra = r0 + ip * 2;
                float xra = x2r[ra], xrb = x2r[ra + 1];
                #pragma unroll
                for (int j = 0; j < 4; ++j) {
                    // t - 2*dot via fma: rounds identically to the reference
                    Dt[ra * PD + c0 + j]       = fmaf(-2.f, lane_lo(acc[ip][j]), xra + xc[j]);
                    Dt[(ra + 1) * PD + c0 + j] = fmaf(-2.f, lane_hi(acc[ip][j]), xrb + xc[j]);
                }
            }
        }
        if (ct + 1 < NTILES) {
            #pragma unroll
            for (int it = 0; it < 4; ++it) {
                int idx = it * NTHREADS + tid;
                int n   = idx & 63;
                int d4  = idx >> 6;
                Bt[(d4 * 4 + 0) * PB + n] = pf[it].x;
                Bt[(d4 * 4 + 1) * PB + n] = pf[it].y;
                Bt[(d4 * 4 + 2) * PB + n] = pf[it].z;
                Bt[(d4 * 4 + 3) * PB + n] = pf[it].w;
            }
        }
        __syncthreads();
    }

    // ---- final scan (last tile) ----
    {
        const int cbase = (NTILES - 1) * TN + sh * 32;
        float b15 = best[KNN - 1];
        #pragma unroll 4
        for (int c = 0; c < 32; ++c) {
            float v = drow[c];
            if (v < b15) {
                best[KNN - 1] = v;
                bidx[KNN - 1] = cbase + c;
                #pragma unroll
                for (int j = KNN - 1; j > 0; --j) {
                    if (best[j] < best[j - 1]) {
                        float tv = best[j]; best[j] = best[j - 1]; best[j - 1] = tv;
                        int   ti = bidx[j]; bidx[j] = bidx[j - 1]; bidx[j - 1] = ti;
                    }
                }
                b15 = best[KNN - 1];
            }
        }
    }
    __syncthreads();   // everyone done with At -> reuse as merge scratch

    // ---- merge the two half-lists per row (stable: ties -> lower index) ----
    float* vals = At;               // 128 rows x 32 entries = 16KB (fits in At)
    int*   idxs = (int*)(At + TM * 32);
    #pragma unroll
    for (int j = 0; j < KNN; ++j) {
        vals[srow * 32 + sh * KNN + j] = best[j];
        idxs[srow * 32 + sh * KNN + j] = bidx[j];
    }
    __syncthreads();

    if (tid < TM) {
        const int row = tid;
        const float* v0 = &vals[row * 32];
        const float* v1 = &vals[row * 32 + KNN];
        const int*   i0 = &idxs[row * 32];
        const int*   i1 = &idxs[row * 32 + KNN];
        int p0 = 0, p1 = 0;
        const int gid  = batch * MP + row0 + row;
        const int off  = batch * MP;
        const int base = gid * KNN;
        #pragma unroll
        for (int t = 0; t < KNN; ++t) {
            float a = (p0 < KNN) ? v0[p0] : __int_as_float(0x7f800000);
            float b = (p1 < KNN) ? v1[p1] : __int_as_float(0x7f800000);
            int   ia = (p0 < KNN) ? i0[p0] : 0x7fffffff;
            int   ib = (p1 < KNN) ? i1[p1] : 0x7fffffff;
            bool take0 = (a < b) || (a == b && ia < ib);
            int sel = take0 ? ia : ib;
            if (take0) ++p0; else ++p1;
            out[base + t] = (float)(sel + off);
        }
        if (write_dst) {
            float fgid = (float)gid;
            #pragma unroll
            for (int t = 0; t < KNN; ++t) out[NEDGES + base + t] = fgid;
        }
    }
}

extern "C" void kernel_launch(void* const* d_in, const int* in_sizes, int n_in,
                              void* d_out, int out_size) {
    // Bind x = largest input (robust to ordering and element/byte units).
    const float* x = (const float*)d_in[0];
    long long best_sz = -1;
    for (int i = 0; i < n_in; ++i) {
        if ((long long)in_sizes[i] > best_sz) {
            best_sz = in_sizes[i];
            x = (const float*)d_in[i];
        }
    }
    const int write_dst = (out_size >= 2 * NEDGES);

    cudaFuncSetAttribute(knn_topk_kernel,
                         cudaFuncAttributeMaxDynamicSharedMemorySize, SMEM_BYTES);
    knn_topk_kernel<<<NB * (MP / TM), NTHREADS, SMEM_BYTES>>>(x, (float*)d_out, write_dst);
}

// round 11
// speedup vs baseline: 2.3831x; 1.6053x over previous
#include <cuda_runtime.h>

// Problem constants (fixed: N=4, M=8192, D=64, k=16)
#define NB 4
#define MP 8192
#define DD 64
#define KNN 16
#define TM 256
#define TN 64
#define NTILES (MP / TN)        // 128
#define NTHREADS 512
#define NEDGES (NB * MP * KNN)  // 524288

#define PA 260   // At pitch (floats)
#define PB 68    // Bt pitch
#define PD 67    // Dt pitch (odd-ish -> conflict-free row scan)

// shared layout (float offsets)
#define SM_AT  0                            // 64 x 260 = 16640
#define SM_BT  (DD * PA)                    // + 64 x 68 = 4352
#define SM_DT  (SM_BT + DD * PB)            // + 256 x 67 = 17152
#define SM_X2R (SM_DT + TM * PD)            // + 256
#define SM_X2C (SM_X2R + TM)                // + 64
#define SMEM_FLOATS (SM_X2C + TN)           // 38464
#define SMEM_BYTES  (SMEM_FLOATS * 4)       // 153,856 B -> 1 CTA/SM, 16 warps

typedef unsigned long long ull;

__device__ __forceinline__ ull ffma2(ull a, ull b, ull c) {
    ull d;
    asm("fma.rn.f32x2 %0, %1, %2, %3;" : "=l"(d) : "l"(a), "l"(b), "l"(c));
    return d;
}
__device__ __forceinline__ ull splat2(float v) {
    ull d;
    unsigned u = __float_as_uint(v);
    asm("mov.b64 %0, {%1, %1};" : "=l"(d) : "r"(u));
    return d;
}
__device__ __forceinline__ float lane_lo(ull v) { return __uint_as_float((unsigned)v); }
__device__ __forceinline__ float lane_hi(ull v) { return __uint_as_float((unsigned)(v >> 32)); }

__global__ __launch_bounds__(NTHREADS, 1)
void knn_topk_kernel(const float* __restrict__ x,
                     float* __restrict__ out,
                     int write_dst) {
    extern __shared__ float sm[];
    float* At  = sm + SM_AT;    // [64][PA]  At[d][m], m=0..255
    float* Bt  = sm + SM_BT;    // [64][PB]  Bt[d][n], n=0..63
    float* Dt  = sm + SM_DT;    // [256][PD] d2 tile
    float* x2r = sm + SM_X2R;
    float* x2c = sm + SM_X2C;

    const int tid   = threadIdx.x;
    const int batch = blockIdx.x >> 5;          // 32 row-tiles per batch
    const int rtile = blockIdx.x & 31;
    const float* xb = x + (size_t)batch * MP * DD;
    const int row0  = rtile * TM;

    // ---- Prologue: A tile (256 x 64) transposed to d-major ----
    #pragma unroll
    for (int it = 0; it < 8; ++it) {
        int idx = it * NTHREADS + tid;          // 0..4095
        int m   = idx & 255;
        int d4  = idx >> 8;                     // 0..15
        float4 v = *reinterpret_cast<const float4*>(xb + (size_t)(row0 + m) * DD + d4 * 4);
        At[(d4 * 4 + 0) * PA + m] = v.x;
        At[(d4 * 4 + 1) * PA + m] = v.y;
        At[(d4 * 4 + 2) * PA + m] = v.z;
        At[(d4 * 4 + 3) * PA + m] = v.w;
    }
    // ---- B tile 0: prefetch to regs, store ----
    float4 pf[2];
    #pragma unroll
    for (int it = 0; it < 2; ++it) {
        int idx = it * NTHREADS + tid;          // 0..1023
        int n   = idx & 63;
        int d4  = idx >> 6;
        pf[it] = *reinterpret_cast<const float4*>(xb + (size_t)n * DD + d4 * 4);
    }
    #pragma unroll
    for (int it = 0; it < 2; ++it) {
        int idx = it * NTHREADS + tid;
        int n   = idx & 63;
        int d4  = idx >> 6;
        Bt[(d4 * 4 + 0) * PB + n] = pf[it].x;
        Bt[(d4 * 4 + 1) * PB + n] = pf[it].y;
        Bt[(d4 * 4 + 2) * PB + n] = pf[it].z;
        Bt[(d4 * 4 + 3) * PB + n] = pf[it].w;
    }
    __syncthreads();

    const int ty = tid >> 4;          // 0..31
    const int tx = tid & 15;          // 0..15
    const int r0 = ty * 8;            // 8 contiguous rows
    const int c0 = tx * 4;            // 4 contiguous cols

    // scan: 2 threads per row, 32 cols each
    const int srow = tid & 255;
    const int sh   = tid >> 8;        // 0 or 1
    const float* drow = &Dt[srow * PD + sh * 32];

    float best[KNN];
    int   bidx[KNN];
    #pragma unroll
    for (int i = 0; i < KNN; ++i) { best[i] = __int_as_float(0x7f800000); bidx[i] = 0; }

    for (int ct = 0; ct < NTILES; ++ct) {
        // ================= P1: scan(ct-1) | norms | prefetch | GEMM(ct) ======
        if (ct > 0) {
            const int cbase = (ct - 1) * TN + sh * 32;
            float b15 = best[KNN - 1];
            #pragma unroll 4
            for (int c = 0; c < 32; ++c) {
                float v = drow[c];
                if (v < b15) {
                    best[KNN - 1] = v;
                    bidx[KNN - 1] = cbase + c;
                    #pragma unroll
                    for (int j = KNN - 1; j > 0; --j) {
                        if (best[j] < best[j - 1]) {
                            float tv = best[j]; best[j] = best[j - 1]; best[j - 1] = tv;
                            int   ti = bidx[j]; bidx[j] = bidx[j - 1]; bidx[j - 1] = ti;
                        }
                    }
                    b15 = best[KNN - 1];
                }
            }
        }
        if (tid < TM && ct == 0) {            // row norms once
            float s = 0.f;
            #pragma unroll
            for (int d = 0; d < DD; ++d) { float a = At[d * PA + tid]; s = fmaf(a, a, s); }
            x2r[tid] = s;
        }
        if (tid < TN) {                        // candidate norms for this tile
            float s = 0.f;
            #pragma unroll
            for (int d = 0; d < DD; ++d) { float b = Bt[d * PB + tid]; s = fmaf(b, b, s); }
            x2c[tid] = s;
        }
        // prefetch next B tile (hidden under GEMM)
        if (ct + 1 < NTILES) {
            const int col0n = (ct + 1) * TN;
            #pragma unroll
            for (int it = 0; it < 2; ++it) {
                int idx = it * NTHREADS + tid;
                int n   = idx & 63;
                int d4  = idx >> 6;
                pf[it] = *reinterpret_cast<const float4*>(xb + (size_t)(col0n + n) * DD + d4 * 4);
            }
        }

        // ---- 256x64x64 GEMM, 8x4 micro-tile, packed f32x2 (rows paired) ----
        ull acc[4][4];
        #pragma unroll
        for (int ip = 0; ip < 4; ++ip)
            #pragma unroll
            for (int j = 0; j < 4; ++j) acc[ip][j] = 0ULL;

        #pragma unroll 2
        for (int k = 0; k < DD; ++k) {
            ulonglong2 a01 = *reinterpret_cast<const ulonglong2*>(&At[k * PA + r0]);
            ulonglong2 a23 = *reinterpret_cast<const ulonglong2*>(&At[k * PA + r0 + 4]);
            float4 bv = *reinterpret_cast<const float4*>(&Bt[k * PB + c0]);
            ull ap[4] = {a01.x, a01.y, a23.x, a23.y};
            float bs[4] = {bv.x, bv.y, bv.z, bv.w};
            #pragma unroll
            for (int j = 0; j < 4; ++j) {
                ull b2 = splat2(bs[j]);
                #pragma unroll
                for (int ip = 0; ip < 4; ++ip)
                    acc[ip][j] = ffma2(ap[ip], b2, acc[ip][j]);
            }
        }
        __syncthreads();   // GEMM reads of Bt done; x2c (and x2r) visible

        // ================= P2: epilogue -> Dt | store prefetched Bt ==========
        {
            float xc[4];
            #pragma unroll
            for (int j = 0; j < 4; ++j) xc[j] = x2c[c0 + j];
            #pragma unroll
            for (int ip = 0; ip < 4; ++ip) {
                int ra = r0 + ip * 2;
                float xra = x2r[ra], xrb = x2r[ra + 1];
                #pragma unroll
                for (int j = 0; j < 4; ++j) {
                    // t - 2*dot via fma: rounds identically to the reference
                    Dt[ra * PD + c0 + j]       = fmaf(-2.f, lane_lo(acc[ip][j]), xra + xc[j]);
                    Dt[(ra + 1) * PD + c0 + j] = fmaf(-2.f, lane_hi(acc[ip][j]), xrb + xc[j]);
                }
            }
        }
        if (ct + 1 < NTILES) {
            #pragma unroll
            for (int it = 0; it < 2; ++it) {
                int idx = it * NTHREADS + tid;
                int n   = idx & 63;
                int d4  = idx >> 6;
                Bt[(d4 * 4 + 0) * PB + n] = pf[it].x;
                Bt[(d4 * 4 + 1) * PB + n] = pf[it].y;
                Bt[(d4 * 4 + 2) * PB + n] = pf[it].z;
                Bt[(d4 * 4 + 3) * PB + n] = pf[it].w;
            }
        }
        __syncthreads();
    }

    // ---- final scan (last tile) ----
    {
        const int cbase = (NTILES - 1) * TN + sh * 32;
        float b15 = best[KNN - 1];
        #pragma unroll 4
        for (int c = 0; c < 32; ++c) {
            float v = drow[c];
            if (v < b15) {
                best[KNN - 1] = v;
                bidx[KNN - 1] = cbase + c;
                #pragma unroll
                for (int j = KNN - 1; j > 0; --j) {
                    if (best[j] < best[j - 1]) {
                        float tv = best[j]; best[j] = best[j - 1]; best[j - 1] = tv;
                        int   ti = bidx[j]; bidx[j] = bidx[j - 1]; bidx[j - 1] = ti;
                    }
                }
                b15 = best[KNN - 1];
            }
        }
    }
    __syncthreads();   // everyone done with At -> reuse as merge scratch

    // ---- merge the two half-lists per row (stable: ties -> lower index) ----
    float* vals = At;                       // 256 x 16 floats = 4096
    int*   idxs = (int*)(At + TM * KNN);    // 256 x 16 ints   = 4096 (fits in At)
    #pragma unroll
    for (int j = 0; j < KNN; ++j) {
        // interleave: [row][half*16 + j] with row stride 32
        At[srow * 32 + sh * KNN + j]                = best[j];
        ((int*)(At + TM * 32))[srow * 32 + sh * KNN + j] = bidx[j];
    }
    __syncthreads();

    if (tid < TM) {
        const int row = tid;
        const float* v0 = &At[row * 32];
        const float* v1 = &At[row * 32 + KNN];
        const int*   i0 = &((int*)(At + TM * 32))[row * 32];
        const int*   i1 = &((int*)(At + TM * 32))[row * 32 + KNN];
        int p0 = 0, p1 = 0;
        const int gid  = batch * MP + row0 + row;
        const int off  = batch * MP;
        const int base = gid * KNN;
        #pragma unroll
        for (int t = 0; t < KNN; ++t) {
            float a = (p0 < KNN) ? v0[p0] : __int_as_float(0x7f800000);
            float b = (p1 < KNN) ? v1[p1] : __int_as_float(0x7f800000);
            int   ia = (p0 < KNN) ? i0[p0] : 0x7fffffff;
            int   ib = (p1 < KNN) ? i1[p1] : 0x7fffffff;
            bool take0 = (a < b) || (a == b && ia < ib);
            int sel = take0 ? ia : ib;
            if (take0) ++p0; else ++p1;
            out[base + t] = (float)(sel + off);
        }
        if (write_dst) {
            float fgid = (float)gid;
            #pragma unroll
            for (int t = 0; t < KNN; ++t) out[NEDGES + base + t] = fgid;
        }
    }
}

extern "C" void kernel_launch(void* const* d_in, const int* in_sizes, int n_in,
                              void* d_out, int out_size) {
    // Bind x = largest input (robust to ordering and element/byte units).
    const float* x = (const float*)d_in[0];
    long long best_sz = -1;
    for (int i = 0; i < n_in; ++i) {
        if ((long long)in_sizes[i] > best_sz) {
            best_sz = in_sizes[i];
            x = (const float*)d_in[i];
        }
    }
    const int write_dst = (out_size >= 2 * NEDGES);

    cudaFuncSetAttribute(knn_topk_kernel,
                         cudaFuncAttributeMaxDynamicSharedMemorySize, SMEM_BYTES);
    knn_topk_kernel<<<NB * (MP / TM), NTHREADS, SMEM_BYTES>>>(x, (float*)d_out, write_dst);
}